// round 5
// baseline (speedup 1.0000x reference)
#include <cuda_runtime.h>
#include <cstdint>

typedef unsigned long long u64;
typedef unsigned int u32;

// Problem geometry
#define CB_K 512
#define CB_C 64
#define HW   4096
#define N_PIX 524288
#define Q_ELEMS 33554432
#define OFF_IDX  Q_ELEMS
#define OFF_LOSS (OFF_IDX + N_PIX)
#define OFF_ENT  (OFF_LOSS + 1)

#define MT 128
#define NTILES (N_PIX / MT)          // 4096
#define THREADS 256

#define EKS 68                       // ek stride (floats): banks (4n+c)%32 conflict-free
#define FTS 136                      // fT stride (floats): banks (8c+m)%32 conflict-free

// smem byte offsets
#define SB_EK   0                    // ek[code][ch] 512x68 f32 = 139264
#define SB_FT   139264               // fT[ch][pix] 64x136 f32 = 34816
#define SB_EE   174080               // E_k 512 f32
#define SB_S    176128               // S[p] 128 f32
#define SB_W    176640               // w[p] 128 f32
#define SB_HIST 177152               // 512 int
#define SB_WIN  179200               // 128 u64 packed (d,k)
#define SB_LANE 180224               // 4 f32
#define SB_EMAX 180240               // 1 int
#define SMEM_TOTAL 180352

__device__ double g_lane[4];
__device__ int    g_counts[CB_K];

__global__ void vq_zero(){
    int t = threadIdx.x;
    if (t < CB_K) g_counts[t] = 0;
    if (t < 4)    g_lane[t] = 0.0;
}

__device__ __forceinline__ void mma_tf32(float* d, const u32* a, const u32* b){
    asm volatile("mma.sync.aligned.m16n8k8.row.col.f32.tf32.tf32.f32 "
        "{%0,%1,%2,%3}, {%4,%5,%6,%7}, {%8,%9}, {%0,%1,%2,%3};"
        : "+f"(d[0]), "+f"(d[1]), "+f"(d[2]), "+f"(d[3])
        : "r"(a[0]), "r"(a[1]), "r"(a[2]), "r"(a[3]), "r"(b[0]), "r"(b[1]));
}

__global__ void __launch_bounds__(THREADS, 1)
vq_mma(const float* __restrict__ x, const float* __restrict__ cb, float* __restrict__ out)
{
    extern __shared__ char smem[];
    float* ek   = (float*)(smem + SB_EK);
    float* fT   = (float*)(smem + SB_FT);
    float* ee   = (float*)(smem + SB_EE);
    float* Sarr = (float*)(smem + SB_S);
    float* warr = (float*)(smem + SB_W);
    int*   hist = (int*)(smem + SB_HIST);
    u64*   win  = (u64*)(smem + SB_WIN);
    float* lane_sum = (float*)(smem + SB_LANE);
    int*   emax_i   = (int*)(smem + SB_EMAX);

    const int tid  = threadIdx.x;
    const int wid  = tid >> 5;
    const int lane = tid & 31;
    const int lg   = lane >> 2;   // groupID
    const int lt   = lane & 3;    // threadID in group

    const int tile = blockIdx.x;
    const int plane = tile >> 5;
    const int pixbase = (tile & 31) * MT;

    // ---- Staging (coalesced LDG.128, conflict-free STS.128) ----
    for (int i = tid; i < CB_K * CB_C / 4; i += THREADS) {
        int k = i >> 4, c4 = i & 15;
        float4 v = *(const float4*)(cb + k * CB_C + 4 * c4);
        *(float4*)(ek + k * EKS + 4 * c4) = v;
    }
    const float* xin = x + (size_t)plane * (CB_C * HW) + pixbase;
    for (int i = tid; i < MT * CB_C / 4; i += THREADS) {
        int c = i >> 5, p4 = i & 31;
        float4 v = *(const float4*)(xin + (size_t)c * HW + 4 * p4);
        *(float4*)(fT + c * FTS + 4 * p4) = v;
    }
    for (int k = tid; k < CB_K; k += THREADS) hist[k] = 0;
    if (tid < MT) win[tid] = ~0ull;
    if (tid < 4)  lane_sum[tid] = 0.f;
    if (tid == 0) *emax_i = 0;
    __syncthreads();

    // E_k exact (sequential fma ascending c), Emax; S[p] exact
    for (int k = tid; k < CB_K; k += THREADS) {
        float s = 0.f;
        #pragma unroll
        for (int c = 0; c < CB_C; ++c) { float e = ek[k * EKS + c]; s = __fmaf_rn(e, e, s); }
        ee[k] = s;
        atomicMax(emax_i, __float_as_int(s));   // positive floats: int order == float order
    }
    if (tid < MT) {
        float s = 0.f;
        #pragma unroll
        for (int c = 0; c < CB_C; ++c) { float v = fT[c * FTS + tid]; s = __fmaf_rn(v, v, s); }
        Sarr[tid] = s;
    }
    __syncthreads();
    if (tid < MT)
        warr[tid] = __fmaf_rn(0.0078125f, __fsqrt_rn(Sarr[tid] * __int_as_float(*emax_i)), 1e-4f);
    __syncthreads();

    // ---- tf32 mma.sync prune + exact verify ----
    const int mbase = (wid >> 2) * 64;     // warps 0-3: pixels 0-63; 4-7: 64-127
    const int nq = wid & 3;

    #pragma unroll 1
    for (int pass = 0; pass < 2; ++pass) {
        const int nbase = pass * 256 + nq * 64;
        float D[4][8][4];
        #pragma unroll
        for (int mt = 0; mt < 4; ++mt)
            #pragma unroll
            for (int nt = 0; nt < 8; ++nt)
                #pragma unroll
                for (int j = 0; j < 4; ++j) D[mt][nt][j] = 0.f;

        #pragma unroll
        for (int ks = 0; ks < 8; ++ks) {
            const int c0 = ks * 8;
            u32 A[4][4], B[8][2];
            #pragma unroll
            for (int mt = 0; mt < 4; ++mt) {
                int r0 = mbase + mt * 16 + lg;
                A[mt][0] = __float_as_uint(fT[(c0 + lt) * FTS + r0]);
                A[mt][1] = __float_as_uint(fT[(c0 + lt) * FTS + r0 + 8]);
                A[mt][2] = __float_as_uint(fT[(c0 + lt + 4) * FTS + r0]);
                A[mt][3] = __float_as_uint(fT[(c0 + lt + 4) * FTS + r0 + 8]);
            }
            #pragma unroll
            for (int nt = 0; nt < 8; ++nt) {
                int n = nbase + nt * 8 + lg;
                B[nt][0] = __float_as_uint(ek[n * EKS + c0 + lt]);
                B[nt][1] = __float_as_uint(ek[n * EKS + c0 + 4 + lt]);
            }
            #pragma unroll
            for (int mt = 0; mt < 4; ++mt)
                #pragma unroll
                for (int nt = 0; nt < 8; ++nt) mma_tf32(D[mt][nt], A[mt], B[nt]);
        }

        // Epilogue: per-row window candidates -> exact verify -> packed atomicMin
        #pragma unroll
        for (int mt = 0; mt < 4; ++mt) {
            #pragma unroll
            for (int half = 0; half < 2; ++half) {      // half 0: rows lg; half 1: rows lg+8
                const int r = mbase + mt * 16 + lg + half * 8;
                const float S_r = Sarr[r];
                float dv[16];
                float lm = 3.4e38f;
                #pragma unroll
                for (int nt = 0; nt < 8; ++nt) {
                    #pragma unroll
                    for (int j = 0; j < 2; ++j) {
                        int n = nbase + nt * 8 + 2 * lt + j;
                        float d = __fadd_rn(__fmaf_rn(-2.f, D[mt][nt][half * 2 + j], S_r), ee[n]);
                        dv[nt * 2 + j] = d;
                        lm = fminf(lm, d);
                    }
                }
                lm = fminf(lm, __shfl_xor_sync(0xffffffffu, lm, 1));
                lm = fminf(lm, __shfl_xor_sync(0xffffffffu, lm, 2));
                const float thr = lm + 2.f * warr[r];
                #pragma unroll
                for (int q = 0; q < 16; ++q) {
                    if (dv[q] <= thr) {
                        int n = nbase + (q >> 1) * 8 + 2 * lt + (q & 1);
                        // exact re-verify: reference two-rounding chain
                        float Dx = 0.f;
                        #pragma unroll
                        for (int c = 0; c < CB_C; ++c)
                            Dx = __fmaf_rn(fT[c * FTS + r], ek[n * EKS + c], Dx);
                        float d = __fadd_rn(__fmaf_rn(-2.f, Dx, S_r), ee[n]);
                        u32 b = __float_as_uint(d);
                        u32 mk = (b & 0x80000000u) ? ~b : (b | 0x80000000u);
                        u64 key = ((u64)mk << 32) | (u32)n;
                        atomicMin(&win[r], key);
                    }
                }
            }
        }
    }
    __syncthreads();

    // ---- Outputs + losses (R3-validated machinery) ----
    if (tid < MT) {
        int kf = (int)(win[tid] & 1023u);
        atomicAdd(&hist[kf], 1);
        out[OFF_IDX + (size_t)(tile * MT + tid)] = (float)kf;
    }
    __syncthreads();

    const int p = tid & 127;
    const int chalf = tid >> 7;
    const int kf = (int)(win[p] & 1023u);

    const bool quantz = (plane >= 2);
    float scaleQ = 1.f, invQ = 1.f;
    if (quantz) {
        int lgp = 31 - __clz(plane);
        int kq = 7 - lgp;
        scaleQ = (float)(1 << kq);
        invQ   = 1.f / (float)(1 << kq);
    }
    float acc = 0.f;
    const int c0 = chalf * 32;
    #pragma unroll
    for (int c = c0; c < c0 + 32; ++c) {
        float q  = ek[kf * EKS + c];
        float xv = fT[c * FTS + p];
        float da = __fsub_rn(q, xv);
        float v  = __fmul_rn(da, da);
        if (quantz) {
            float mm = __fsub_rn(__fmaf_rn(v, scaleQ, 8388608.f), 8388608.f);
            acc = __fmaf_rn(mm, invQ, acc);
        } else acc = __fadd_rn(v, acc);
        out[(size_t)plane * (CB_C * HW) + (size_t)c * HW + pixbase + p] = __fadd_rn(xv, da);
    }
    atomicAdd(&lane_sum[p & 3], acc);
    __syncthreads();
    if (tid < 4) atomicAdd(&g_lane[tid], (double)lane_sum[tid]);
    for (int k = tid; k < CB_K; k += THREADS) {
        int c = hist[k];
        if (c) atomicAdd(&g_counts[k], c);
    }
}

__global__ void vq_finalize(float* __restrict__ out) {
    __shared__ double red[CB_K];
    int t = threadIdx.x;
    int c = g_counts[t];
    double pr = (double)c / (double)N_PIX;
    red[t] = (c > 0) ? (-pr * log2(pr)) : 0.0;
    __syncthreads();
    for (int o = CB_K / 2; o > 0; o >>= 1) {
        if (t < o) red[t] += red[t + o];
        __syncthreads();
    }
    if (t == 0) {
        out[OFF_ENT] = (float)red[0];
        float s0 = (float)g_lane[0], s1 = (float)g_lane[1];
        float s2 = (float)g_lane[2], s3 = (float)g_lane[3];
        float hs = __fadd_rn(__fadd_rn(s0, s1), __fadd_rn(s2, s3));
        float L  = hs * (1.f / 33554432.f);
        out[OFF_LOSS] = __fadd_rn(L, 0.25f * L);
    }
}

extern "C" void kernel_launch(void* const* d_in, const int* in_sizes, int n_in,
                              void* d_out, int out_size) {
    const float* x  = (const float*)d_in[0];
    const float* cb = (const float*)d_in[1];
    float* out = (float*)d_out;
    cudaFuncSetAttribute(vq_mma, cudaFuncAttributeMaxDynamicSharedMemorySize, SMEM_TOTAL);
    vq_zero<<<1, CB_K>>>();
    vq_mma<<<NTILES, THREADS, SMEM_TOTAL>>>(x, cb, out);
    vq_finalize<<<1, CB_K>>>(out);
}